// round 10
// baseline (speedup 1.0000x reference)
#include <cuda_runtime.h>
#include <cuda_bf16.h>
#include <math.h>
#include <float.h>
#include <stdint.h>

#define B_   4
#define S_   2048
#define DH   512
#define H_   8
#define HD   64
#define M_   (B_*S_)
#define BH_  (B_*H_)
#define SPAD 200   // padded smem row stride (elems); 400B -> ldmatrix conflict-free

// -------- scratch --------
__device__ float g_v [BH_*S_*HD];
__device__ float g_ao[M_*DH];
__device__ float g_o [M_*DH];
__device__ float g_attn_fb[(size_t)BH_*S_*S_];
__device__ __align__(16) __nv_bfloat16 g_qs[(size_t)BH_*S_*192];   // [Qhi,Qhi,Qlo]
__device__ __align__(16) __nv_bfloat16 g_ks[(size_t)BH_*S_*192];   // [Khi,Klo,Khi]
__device__ __align__(16) __nv_bfloat16 g_vt[(size_t)BH_*HD*6144];  // V^T split per 64-chunk
__device__ __align__(16) __nv_bfloat16 g_xs [(size_t)M_*1536];     // X  split [hi,hi,lo]
__device__ __align__(16) __nv_bfloat16 g_aos[(size_t)M_*1536];     // AO split [hi,hi,lo]
__device__ __align__(16) __nv_bfloat16 g_wt [(size_t)4*512*1536];  // W^T split [hi,lo,hi]

// ---------------- helpers ----------------
__device__ __forceinline__ uint32_t smem_u32(const void* p) {
    uint32_t a;
    asm("{ .reg .u64 t; cvta.to.shared.u64 t, %1; cvt.u32.u64 %0, t; }" : "=r"(a) : "l"(p));
    return a;
}
__device__ __forceinline__ void cp16(uint32_t s, const void* g) {
    asm volatile("cp.async.cg.shared.global [%0], [%1], 16;" :: "r"(s), "l"(g) : "memory");
}
#define CP_COMMIT() asm volatile("cp.async.commit_group;" ::: "memory")
#define CP_WAIT0()  asm volatile("cp.async.wait_group 0;" ::: "memory")
#define CP_WAIT1()  asm volatile("cp.async.wait_group 1;" ::: "memory")
__device__ __forceinline__ void ldm4(uint32_t* r, uint32_t addr) {
    asm volatile("ldmatrix.sync.aligned.m8n8.x4.shared.b16 {%0,%1,%2,%3}, [%4];"
        : "=r"(r[0]), "=r"(r[1]), "=r"(r[2]), "=r"(r[3]) : "r"(addr));
}
__device__ __forceinline__ void mma16816(float* d, const uint32_t* a, uint32_t b0, uint32_t b1) {
    asm volatile("mma.sync.aligned.m16n8k16.row.col.f32.bf16.bf16.f32 "
        "{%0,%1,%2,%3}, {%4,%5,%6,%7}, {%8,%9}, {%0,%1,%2,%3};"
        : "+f"(d[0]), "+f"(d[1]), "+f"(d[2]), "+f"(d[3])
        : "r"(a[0]), "r"(a[1]), "r"(a[2]), "r"(a[3]), "r"(b0), "r"(b1));
}
__device__ __forceinline__ uint32_t pack_bf2(__nv_bfloat16 a, __nv_bfloat16 b) {
    return ((uint32_t)__bfloat16_as_ushort(b) << 16) | (uint32_t)__bfloat16_as_ushort(a);
}
__device__ __forceinline__ void split2(float x, float y, uint32_t& hi, uint32_t& lo) {
    __nv_bfloat16 hx = __float2bfloat16_rn(x), hy = __float2bfloat16_rn(y);
    hi = pack_bf2(hx, hy);
    lo = pack_bf2(__float2bfloat16_rn(x - __bfloat162float(hx)),
                  __float2bfloat16_rn(y - __bfloat162float(hy)));
}

// ============================================================================
// x_prep: fp32 [M][512] -> bf16 split [M][1536] = [hi, hi, lo]
// ============================================================================
__global__ __launch_bounds__(256) void x_prep(
    const float* __restrict__ src, __nv_bfloat16* __restrict__ dst)
{
    int idx = blockIdx.x * 256 + threadIdx.x;
    int row = idx >> 7, cc = (idx & 127) * 4;
    float4 v = *(const float4*)&src[(size_t)row * 512 + cc];
    uint32_t h0, l0, h1, l1;
    split2(v.x, v.y, h0, l0);
    split2(v.z, v.w, h1, l1);
    __nv_bfloat16* d = dst + (size_t)row * 1536 + cc;
    uint2 hi = {h0, h1}, lo = {l0, l1};
    *(uint2*)(d)        = hi;
    *(uint2*)(d + 512)  = hi;
    *(uint2*)(d + 1024) = lo;
}

// ============================================================================
// w_prep: W [512][512] fp32 -> g_wt[z] [n][1536] = [Whi, Wlo, Whi] transposed
// ============================================================================
__global__ __launch_bounds__(256) void w_prep(
    const float* __restrict__ Wq, const float* __restrict__ Wk,
    const float* __restrict__ Wv, const float* __restrict__ Wo)
{
    __shared__ float ts[64][65];
    const int tid = threadIdx.x, z = blockIdx.z;
    const float* W = (z == 0) ? Wq : (z == 1) ? Wk : (z == 2) ? Wv : Wo;
    const int k0 = blockIdx.x * 64, n0 = blockIdx.y * 64;
    #pragma unroll
    for (int j = 0; j < 4; j++) {
        int lin = tid + j * 256;
        int r = lin >> 4, c = (lin & 15) * 4;
        float4 v = *(const float4*)&W[(size_t)(k0 + r) * 512 + n0 + c];
        ts[r][c] = v.x; ts[r][c+1] = v.y; ts[r][c+2] = v.z; ts[r][c+3] = v.w;
    }
    __syncthreads();
    const int nn = tid >> 2, kk = (tid & 3) * 16;
    uint32_t hp[8], lp[8];
    #pragma unroll
    for (int j = 0; j < 8; j++)
        split2(ts[kk + 2*j][nn], ts[kk + 2*j + 1][nn], hp[j], lp[j]);
    __nv_bfloat16* dst = g_wt + ((size_t)z * 512 + n0 + nn) * 1536 + k0 + kk;
    uint4 h0 = {hp[0],hp[1],hp[2],hp[3]}, h1 = {hp[4],hp[5],hp[6],hp[7]};
    uint4 l0 = {lp[0],lp[1],lp[2],lp[3]}, l1 = {lp[4],lp[5],lp[6],lp[7]};
    *(uint4*)(dst)          = h0;  *(uint4*)(dst + 8)        = h1;
    *(uint4*)(dst + 512)    = l0;  *(uint4*)(dst + 512 + 8)  = l1;
    *(uint4*)(dst + 1024)   = h0;  *(uint4*)(dst + 1024 + 8) = h1;
}

// ============================================================================
// proj_mma: 512 threads, 16 warps (4x4 grid of 32x32 warp tiles).
// C[128,128] tile = A @ Wt^T, 8 chunks K'=192, cp.async 2-stage pipeline.
// mode = modeBase + blockIdx.z: 0 fp32 out, 1 q-split, 2 k-split, 3 v-scatter.
// ============================================================================
#define PJ_STAGE (2*128*SPAD)
#define PJ_SMEM  (2*PJ_STAGE*2)

__global__ __launch_bounds__(512) void proj_mma(
    const __nv_bfloat16* __restrict__ A, const __nv_bfloat16* __restrict__ WtBase,
    const float* __restrict__ b0, const float* __restrict__ b1,
    const float* __restrict__ b2, const float* __restrict__ pe,
    float* __restrict__ outf, int modeBase)
{
    extern __shared__ __nv_bfloat16 sm[];
    const int tid = threadIdx.x, wid = tid >> 5, lane = tid & 31;
    const int colBase = blockIdx.x * 128, rowBase = blockIdx.y * 128;
    const int z = blockIdx.z;
    const int mode = modeBase + z;
    const __nv_bfloat16* Wt = WtBase + (size_t)z * 512 * 1536;
    const float* bias = (z == 0) ? b0 : (z == 1) ? b1 : b2;

    const uint32_t sbase = smem_u32(sm);
    const int wm = (wid & 3) * 32, wn = (wid >> 2) * 32;
    const uint32_t aOff = (((wm + (lane & 15)) * SPAD) + ((lane >> 4) * 8)) << 1;
    const int brow = (lane & 7) + ((lane >> 4) << 3);
    const int bcol = ((lane >> 3) & 1) * 8;
    const uint32_t bOff = (((128*SPAD) + (wn + brow) * SPAD) + bcol) << 1;

    auto load_stage = [&](int ck, int st) {
        const __nv_bfloat16* Ap = A  + (size_t)rowBase * 1536 + ck * 192;
        const __nv_bfloat16* Bp = Wt + (size_t)colBase * 1536 + ck * 192;
        uint32_t sa = sbase + (uint32_t)st * PJ_STAGE * 2;
        #pragma unroll
        for (int t = 0; t < 6; t++) {
            int idx = tid + t * 512;
            int row = idx / 24, cc = (idx % 24) * 8;
            cp16(sa + ((row*SPAD + cc) << 1),            Ap + (size_t)row * 1536 + cc);
            cp16(sa + ((128*SPAD + row*SPAD + cc) << 1), Bp + (size_t)row * 1536 + cc);
        }
        CP_COMMIT();
    };

    float acc[2][4][4];
    #pragma unroll
    for (int i = 0; i < 2; i++)
        #pragma unroll
        for (int j = 0; j < 4; j++)
            #pragma unroll
            for (int k = 0; k < 4; k++) acc[i][j][k] = 0.f;

    load_stage(0, 0);
    load_stage(1, 1);

    for (int ck = 0; ck < 8; ck++) {
        const int st = ck & 1;
        if (ck < 6) { CP_WAIT1(); } else { CP_WAIT0(); }
        __syncthreads();
        const uint32_t stageB = sbase + (uint32_t)st * PJ_STAGE * 2;
        #pragma unroll
        for (int k0 = 0; k0 < 192; k0 += 16) {
            uint32_t a[2][4], bb[2][4];
            ldm4(a[0], stageB + aOff + (k0 << 1));
            ldm4(a[1], stageB + aOff + ((16*SPAD + k0) << 1));
            ldm4(bb[0], stageB + bOff + (k0 << 1));
            ldm4(bb[1], stageB + bOff + ((16*SPAD + k0) << 1));
            #pragma unroll
            for (int mt = 0; mt < 2; mt++)
                #pragma unroll
                for (int nt = 0; nt < 4; nt++)
                    mma16816(acc[mt][nt], a[mt], bb[nt>>1][(nt&1)*2], bb[nt>>1][(nt&1)*2+1]);
        }
        __syncthreads();
        if (ck + 2 < 8) load_stage(ck + 2, st);
    }

    const int g = lane >> 2, tg = lane & 3;
    #pragma unroll
    for (int mt = 0; mt < 2; mt++) {
        #pragma unroll
        for (int nt = 0; nt < 4; nt++) {
            int c = colBase + wn + nt*8 + tg*2;
            float bx = bias[c], by = bias[c+1];
            int h = c >> 6, d = c & 63;
            #pragma unroll
            for (int half = 0; half < 2; half++) {
                int r = rowBase + wm + mt*16 + g + half*8;
                int bb2 = r >> 11, s = r & 2047;
                float vx = acc[mt][nt][half*2]     + bx;
                float vy = acc[mt][nt][half*2 + 1] + by;
                if (mode == 0) {
                    float2 o = {vx, vy};
                    *(float2*)&outf[(size_t)r * 512 + c] = o;
                } else if (mode == 3) {
                    float2 o = {vx, vy};
                    *(float2*)&g_v[(((size_t)bb2 * H_ + h) * S_ + s) * HD + d] = o;
                } else {
                    float2 p = *(const float2*)&pe[(size_t)s * DH + c];
                    vx += p.x; vy += p.y;
                    uint32_t hi, lo;
                    split2(vx, vy, hi, lo);
                    __nv_bfloat16* base = (mode == 1 ? g_qs : g_ks)
                        + ((size_t)(bb2 * H_ + h) * S_ + s) * 192 + d;
                    if (mode == 1) {
                        *(uint32_t*)(base) = hi; *(uint32_t*)(base+64) = hi; *(uint32_t*)(base+128) = lo;
                    } else {
                        *(uint32_t*)(base) = hi; *(uint32_t*)(base+64) = lo; *(uint32_t*)(base+128) = hi;
                    }
                }
            }
        }
    }
}

// ============================================================================
// v_prep: g_v [bh][s][64] -> g_vt [bh][d][6144]; per 64-chunk: [Vhi,Vlo,Vhi]
// ============================================================================
__global__ __launch_bounds__(256) void v_prep()
{
    __shared__ float ts[64][65];
    const int tid = threadIdx.x, ch = blockIdx.x, bh = blockIdx.y;
    const float* vsrc = g_v + ((size_t)bh * S_ + ch * 64) * HD;
    #pragma unroll
    for (int j = 0; j < 4; j++) {
        int lin = tid + j * 256;
        int r = lin >> 4, cc = (lin & 15) * 4;
        float4 v = *(const float4*)(vsrc + (size_t)r * HD + cc);
        ts[r][cc] = v.x; ts[r][cc+1] = v.y; ts[r][cc+2] = v.z; ts[r][cc+3] = v.w;
    }
    __syncthreads();
    const int n = tid & 63, rg = (tid >> 6) * 16;
    uint32_t hp[8], lp[8];
    #pragma unroll
    for (int q = 0; q < 8; q++)
        split2(ts[rg + 2*q][n], ts[rg + 2*q + 1][n], hp[q], lp[q]);
    __nv_bfloat16* dst = g_vt + ((size_t)bh * HD + n) * 6144 + (size_t)ch * 192;
    uint4 h0 = {hp[0],hp[1],hp[2],hp[3]}, h1 = {hp[4],hp[5],hp[6],hp[7]};
    uint4 l0 = {lp[0],lp[1],lp[2],lp[3]}, l1 = {lp[4],lp[5],lp[6],lp[7]};
    *(uint4*)(dst + rg)        = h0;  *(uint4*)(dst + rg + 8)       = h1;
    *(uint4*)(dst + 64 + rg)   = l0;  *(uint4*)(dst + 64 + rg + 8)  = l1;
    *(uint4*)(dst + 128 + rg)  = h0;  *(uint4*)(dst + 128 + rg + 8) = h1;
}

// ============================================================================
// scores_mma: 512 threads, 16 warps (4x4 grid of 32x32 warp tiles).
// 128x128 tile/CTA, split-bf16 K'=192.
// ============================================================================
#define SC_SMEM (2*128*SPAD*2)

__global__ __launch_bounds__(512) void scores_mma(
    const int* __restrict__ mask, float* __restrict__ attn)
{
    extern __shared__ __nv_bfloat16 sm[];
    __nv_bfloat16* sA = sm;
    __nv_bfloat16* sB = sm + 128*SPAD;
    const int tid = threadIdx.x, wid = tid >> 5, lane = tid & 31;
    const int nBase = blockIdx.x * 128, mBase = blockIdx.y * 128, bh = blockIdx.z;
    const int b = bh >> 3;

    const __nv_bfloat16* qs = g_qs + ((size_t)bh * S_ + mBase) * 192;
    const __nv_bfloat16* ks = g_ks + ((size_t)bh * S_ + nBase) * 192;
    #pragma unroll
    for (int t = 0; t < 6; t++) {
        int idx = tid + t * 512;
        int row = idx / 24, cc = (idx % 24) * 8;
        cp16(smem_u32(&sA[row*SPAD + cc]), qs + (size_t)row * 192 + cc);
        cp16(smem_u32(&sB[row*SPAD + cc]), ks + (size_t)row * 192 + cc);
    }
    CP_COMMIT();
    CP_WAIT0();
    __syncthreads();

    const int wm = (wid & 3) * 32, wn = (wid >> 2) * 32;
    uint32_t aBase = smem_u32(sA) + ((((wm + (lane & 15)) * SPAD) + ((lane >> 4) * 8)) << 1);
    const int brow = (lane & 7) + ((lane >> 4) << 3);
    const int bcol = ((lane >> 3) & 1) * 8;
    uint32_t bBase = smem_u32(sB) + ((((wn + brow) * SPAD) + bcol) << 1);

    float acc[2][4][4];
    #pragma unroll
    for (int i = 0; i < 2; i++)
        #pragma unroll
        for (int j = 0; j < 4; j++)
            #pragma unroll
            for (int k = 0; k < 4; k++) acc[i][j][k] = 0.f;

    #pragma unroll
    for (int k0 = 0; k0 < 192; k0 += 16) {
        uint32_t a[2][4], bb[2][4];
        ldm4(a[0], aBase + (k0 << 1));
        ldm4(a[1], aBase + ((16*SPAD + k0) << 1));
        ldm4(bb[0], bBase + (k0 << 1));
        ldm4(bb[1], bBase + ((16*SPAD + k0) << 1));
        #pragma unroll
        for (int mt = 0; mt < 2; mt++)
            #pragma unroll
            for (int nt = 0; nt < 4; nt++)
                mma16816(acc[mt][nt], a[mt], bb[nt>>1][(nt&1)*2], bb[nt>>1][(nt&1)*2+1]);
    }

    const int g = lane >> 2, tg = lane & 3;
    #pragma unroll
    for (int mt = 0; mt < 2; mt++) {
        #pragma unroll
        for (int nt = 0; nt < 4; nt++) {
            int col = nBase + wn + nt*8 + tg*2;
            int r0 = mBase + wm + mt*16 + g;
            int2 m0 = *(const int2*)&mask[((size_t)b * S_ + r0) * S_ + col];
            float2 o0;
            o0.x = m0.x ? acc[mt][nt][0]*0.125f : -FLT_MAX;
            o0.y = m0.y ? acc[mt][nt][1]*0.125f : -FLT_MAX;
            *(float2*)&attn[((size_t)bh * S_ + r0) * S_ + col] = o0;
            int r1 = r0 + 8;
            int2 m1 = *(const int2*)&mask[((size_t)b * S_ + r1) * S_ + col];
            float2 o1;
            o1.x = m1.x ? acc[mt][nt][2]*0.125f : -FLT_MAX;
            o1.y = m1.y ? acc[mt][nt][3]*0.125f : -FLT_MAX;
            *(float2*)&attn[((size_t)bh * S_ + r1) * S_ + col] = o1;
        }
    }
}

// ============================================================================
// pv_mma: 512 threads, 16 warps (4x4 grid of 32x16 warp tiles).
// O[128,64] = P[128,2048] @ V; 32 chunks of K'=192, P split in-kernel.
// ============================================================================
#define PV_SMEM ((128*SPAD + 64*SPAD)*2)

__global__ __launch_bounds__(512) void pv_mma(const float* __restrict__ attn)
{
    extern __shared__ __nv_bfloat16 sm[];
    __nv_bfloat16* sA = sm;
    __nv_bfloat16* sB = sm + 128*SPAD;
    const int tid = threadIdx.x, wid = tid >> 5, lane = tid & 31;
    const int mBase = blockIdx.x * 128, bh = blockIdx.y;
    const int b = bh >> 3, h = bh & 7;

    const float* prow = attn + ((size_t)bh * S_ + mBase) * S_;
    const __nv_bfloat16* vt = g_vt + (size_t)bh * HD * 6144;

    const int wm = (wid & 3) * 32, wn = (wid >> 2) * 16;
    uint32_t aBase = smem_u32(sA) + ((((wm + (lane & 15)) * SPAD) + ((lane >> 4) * 8)) << 1);
    const int brow = (lane & 7) + ((lane >> 4) << 3);
    const int bcol = ((lane >> 3) & 1) * 8;
    uint32_t bBase = smem_u32(sB) + ((((wn + brow) * SPAD) + bcol) << 1);

    float acc[2][2][4];
    #pragma unroll
    for (int i = 0; i < 2; i++)
        #pragma unroll
        for (int j = 0; j < 2; j++)
            #pragma unroll
            for (int k = 0; k < 4; k++) acc[i][j][k] = 0.f;

    for (int ch = 0; ch < 32; ch++) {
        __syncthreads();
        #pragma unroll
        for (int j = 0; j < 3; j++) {
            int idx = tid + j * 512;
            int n = idx / 24, cc = (idx % 24) * 8;
            cp16(smem_u32(&sB[n*SPAD + cc]), vt + (size_t)n * 6144 + (size_t)ch * 192 + cc);
        }
        CP_COMMIT();
        const int s0 = ch * 64;
        #pragma unroll
        for (int j = 0; j < 4; j++) {
            int lin = tid + j * 512;
            int row = lin >> 4, l = (lin & 15) * 4;
            float4 p = *(const float4*)(prow + (size_t)row * S_ + s0 + l);
            uint32_t h0, l0, h1, l1;
            split2(p.x, p.y, h0, l0);
            split2(p.z, p.w, h1, l1);
            uint2 hi = {h0, h1}, lo = {l0, l1};
            *(uint2*)&sA[row*SPAD + l]       = hi;
            *(uint2*)&sA[row*SPAD + 64 + l]  = hi;
            *(uint2*)&sA[row*SPAD + 128 + l] = lo;
        }
        CP_WAIT0();
        __syncthreads();
        #pragma unroll
        for (int k0 = 0; k0 < 192; k0 += 16) {
            uint32_t a[2][4], bb[4];
            ldm4(a[0], aBase + (k0 << 1));
            ldm4(a[1], aBase + ((16*SPAD + k0) << 1));
            ldm4(bb, bBase + (k0 << 1));
            #pragma unroll
            for (int mt = 0; mt < 2; mt++)
                #pragma unroll
                for (int nt = 0; nt < 2; nt++)
                    mma16816(acc[mt][nt], a[mt], bb[nt*2], bb[nt*2+1]);
        }
    }

    const int g = lane >> 2, tg = lane & 3;
    #pragma unroll
    for (int mt = 0; mt < 2; mt++) {
        #pragma unroll
        for (int nt = 0; nt < 2; nt++) {
            int col = h * 64 + wn + nt*8 + tg*2;
            int r0 = mBase + wm + mt*16 + g;
            float2 o0 = {acc[mt][nt][0], acc[mt][nt][1]};
            float2 o1 = {acc[mt][nt][2], acc[mt][nt][3]};
            *(float2*)&g_ao[((size_t)b * S_ + r0) * DH + col] = o0;
            *(float2*)&g_ao[((size_t)b * S_ + r0 + 8) * DH + col] = o1;
        }
    }
}

// ============================================================================
// Row softmax in place; one block per row.
// ============================================================================
__global__ __launch_bounds__(256) void softmax_kernel(float* __restrict__ attn)
{
    __shared__ float red[8];
    const int tid = threadIdx.x;
    float4* p = (float4*)(attn + (size_t)blockIdx.x * S_);
    float4 v0 = p[tid], v1 = p[tid + 256];
    float mx = fmaxf(fmaxf(fmaxf(v0.x,v0.y), fmaxf(v0.z,v0.w)),
                     fmaxf(fmaxf(v1.x,v1.y), fmaxf(v1.z,v1.w)));
    #pragma unroll
    for (int o = 16; o > 0; o >>= 1) mx = fmaxf(mx, __shfl_xor_sync(~0u, mx, o));
    if ((tid & 31) == 0) red[tid >> 5] = mx;
    __syncthreads();
    mx = red[0];
    #pragma unroll
    for (int i = 1; i < 8; i++) mx = fmaxf(mx, red[i]);
    __syncthreads();
    v0.x = __expf(v0.x - mx); v0.y = __expf(v0.y - mx);
    v0.z = __expf(v0.z - mx); v0.w = __expf(v0.w - mx);
    v1.x = __expf(v1.x - mx); v1.y = __expf(v1.y - mx);
    v1.z = __expf(v1.z - mx); v1.w = __expf(v1.w - mx);
    float s = v0.x+v0.y+v0.z+v0.w + v1.x+v1.y+v1.z+v1.w;
    #pragma unroll
    for (int o = 16; o > 0; o >>= 1) s += __shfl_xor_sync(~0u, s, o);
    if ((tid & 31) == 0) red[tid >> 5] = s;
    __syncthreads();
    s = red[0];
    #pragma unroll
    for (int i = 1; i < 8; i++) s += red[i];
    float inv = 1.f / s;
    v0.x *= inv; v0.y *= inv; v0.z *= inv; v0.w *= inv;
    v1.x *= inv; v1.y *= inv; v1.z *= inv; v1.w *= inv;
    p[tid] = v0; p[tid + 256] = v1;
}

// ============================================================================
// LayerNorm (512) per row.
// ============================================================================
__global__ __launch_bounds__(128) void ln_kernel(
    const float* __restrict__ gamma, const float* __restrict__ beta,
    float* __restrict__ out)
{
    __shared__ float red[8];
    const int r = blockIdx.x, tid = threadIdx.x;
    float4 v = *(const float4*)&g_o[(size_t)r * 512 + tid * 4];
    float s  = v.x + v.y + v.z + v.w;
    float sq = v.x*v.x + v.y*v.y + v.z*v.z + v.w*v.w;
    #pragma unroll
    for (int o = 16; o > 0; o >>= 1) {
        s  += __shfl_xor_sync(~0u, s,  o);
        sq += __shfl_xor_sync(~0u, sq, o);
    }
    if ((tid & 31) == 0) { red[tid >> 5] = s; red[4 + (tid >> 5)] = sq; }
    __syncthreads();
    if (tid < 32) {
        float a  = (tid < 4) ? red[tid]     : 0.f;
        float b2 = (tid < 4) ? red[4 + tid] : 0.f;
        #pragma unroll
        for (int o = 2; o > 0; o >>= 1) {
            a  += __shfl_xor_sync(~0u, a,  o);
            b2 += __shfl_xor_sync(~0u, b2, o);
        }
        if (tid == 0) { red[0] = a; red[1] = b2; }
    }
    __syncthreads();
    float mean = red[0] * (1.f / 512.f);
    float var  = red[1] * (1.f / 512.f) - mean * mean;
    float inv  = rsqrtf(var + 1e-5f);
    int c = tid * 4;
    float4 g4 = *(const float4*)&gamma[c];
    float4 b4 = *(const float4*)&beta[c];
    float4 o4;
    o4.x = (v.x - mean) * inv * g4.x + b4.x;
    o4.y = (v.y - mean) * inv * g4.y + b4.y;
    o4.z = (v.z - mean) * inv * g4.z + b4.z;
    o4.w = (v.w - mean) * inv * g4.w + b4.w;
    *(float4*)&out[(size_t)r * 512 + c] = o4;
}

// ============================================================================
extern "C" void kernel_launch(void* const* d_in, const int* in_sizes, int n_in,
                              void* d_out, int out_size)
{
    const float* x    = (const float*)d_in[0];
    const int*   mask = (const int*)  d_in[1];
    const float* Wq   = (const float*)d_in[2];
    const float* bq   = (const float*)d_in[3];
    const float* Wk   = (const float*)d_in[4];
    const float* bk   = (const float*)d_in[5];
    const float* Wv   = (const float*)d_in[6];
    const float* bv   = (const float*)d_in[7];
    const float* pe   = (const float*)d_in[8];
    const float* Wo   = (const float*)d_in[9];
    const float* bo   = (const float*)d_in[10];
    const float* gam  = (const float*)d_in[11];
    const float* bet  = (const float*)d_in[12];
    float* out = (float*)d_out;

    float *aop, *op, *fb;
    __nv_bfloat16 *xsp, *aosp, *wtp;
    cudaGetSymbolAddress((void**)&aop,  g_ao);
    cudaGetSymbolAddress((void**)&op,   g_o);
    cudaGetSymbolAddress((void**)&fb,   g_attn_fb);
    cudaGetSymbolAddress((void**)&xsp,  g_xs);
    cudaGetSymbolAddress((void**)&aosp, g_aos);
    cudaGetSymbolAddress((void**)&wtp,  g_wt);

    const size_t out_elems  = (size_t)M_ * DH;
    const size_t attn_elems = (size_t)BH_ * S_ * S_;
    int write_attn = ((size_t)out_size >= out_elems + attn_elems) ? 1 : 0;
    float* attn_buf = write_attn ? (out + out_elems) : fb;

    cudaFuncSetAttribute(scores_mma, cudaFuncAttributeMaxDynamicSharedMemorySize, SC_SMEM);
    cudaFuncSetAttribute(pv_mma,     cudaFuncAttributeMaxDynamicSharedMemorySize, PV_SMEM);
    cudaFuncSetAttribute(proj_mma,   cudaFuncAttributeMaxDynamicSharedMemorySize, PJ_SMEM);

    x_prep<<<M_*128/256, 256>>>(x, xsp);
    w_prep<<<dim3(8, 8, 4), 256>>>(Wq, Wk, Wv, Wo);

    // fused QKV: z=0 -> Q (mode 1), z=1 -> K (mode 2), z=2 -> V (mode 3)
    proj_mma<<<dim3(4, 64, 3), 512, PJ_SMEM>>>(xsp, wtp, bq, bk, bv, pe, nullptr, 1);
    v_prep<<<dim3(32, 32), 256>>>();

    scores_mma<<<dim3(16, 16, 32), 512, SC_SMEM>>>(mask, attn_buf);
    softmax_kernel<<<BH_*S_, 256>>>(attn_buf);
    pv_mma<<<dim3(16, 32), 512, PV_SMEM>>>(attn_buf);

    x_prep<<<M_*128/256, 256>>>(aop, aosp);
    proj_mma<<<dim3(4, 64, 1), 512, PJ_SMEM>>>(aosp, wtp + (size_t)3*512*1536,
                                               bo, bo, bo, nullptr, op, 0);
    ln_kernel<<<M_, 128>>>(gam, bet, out);
}

// round 11
// speedup vs baseline: 1.0487x; 1.0487x over previous
#include <cuda_runtime.h>
#include <cuda_bf16.h>
#include <math.h>
#include <float.h>
#include <stdint.h>

#define B_   4
#define S_   2048
#define DH   512
#define H_   8
#define HD   64
#define M_   (B_*S_)
#define BH_  (B_*H_)
#define SPAD 200   // padded smem row stride (elems); 400B -> ldmatrix conflict-free

// -------- scratch --------
__device__ float g_v [BH_*S_*HD];
__device__ float g_ao[M_*DH];
__device__ float g_o [M_*DH];
__device__ float g_attn_fb[(size_t)BH_*S_*S_];
__device__ float2 g_part[(size_t)BH_*S_*32];   // per (row, ntile*2+colhalf) stats
__device__ float2 g_stats[(size_t)BH_*S_];     // per row: (max, 1/sum)
__device__ __align__(16) __nv_bfloat16 g_qs[(size_t)BH_*S_*192];   // [Qhi,Qhi,Qlo]
__device__ __align__(16) __nv_bfloat16 g_ks[(size_t)BH_*S_*192];   // [Khi,Klo,Khi]
__device__ __align__(16) __nv_bfloat16 g_vt[(size_t)BH_*HD*6144];  // V^T split per 64-chunk
__device__ __align__(16) __nv_bfloat16 g_xs [(size_t)M_*1536];     // X  split [hi,hi,lo]
__device__ __align__(16) __nv_bfloat16 g_aos[(size_t)M_*1536];     // AO split [hi,hi,lo]
__device__ __align__(16) __nv_bfloat16 g_wt [(size_t)4*512*1536];  // W^T split [hi,lo,hi]

// ---------------- helpers ----------------
__device__ __forceinline__ uint32_t smem_u32(const void* p) {
    uint32_t a;
    asm("{ .reg .u64 t; cvta.to.shared.u64 t, %1; cvt.u32.u64 %0, t; }" : "=r"(a) : "l"(p));
    return a;
}
__device__ __forceinline__ void cp16(uint32_t s, const void* g) {
    asm volatile("cp.async.cg.shared.global [%0], [%1], 16;" :: "r"(s), "l"(g) : "memory");
}
#define CP_COMMIT() asm volatile("cp.async.commit_group;" ::: "memory")
#define CP_WAIT0()  asm volatile("cp.async.wait_group 0;" ::: "memory")
#define CP_WAIT1()  asm volatile("cp.async.wait_group 1;" ::: "memory")
__device__ __forceinline__ void ldm4(uint32_t* r, uint32_t addr) {
    asm volatile("ldmatrix.sync.aligned.m8n8.x4.shared.b16 {%0,%1,%2,%3}, [%4];"
        : "=r"(r[0]), "=r"(r[1]), "=r"(r[2]), "=r"(r[3]) : "r"(addr));
}
__device__ __forceinline__ void mma16816(float* d, const uint32_t* a, uint32_t b0, uint32_t b1) {
    asm volatile("mma.sync.aligned.m16n8k16.row.col.f32.bf16.bf16.f32 "
        "{%0,%1,%2,%3}, {%4,%5,%6,%7}, {%8,%9}, {%0,%1,%2,%3};"
        : "+f"(d[0]), "+f"(d[1]), "+f"(d[2]), "+f"(d[3])
        : "r"(a[0]), "r"(a[1]), "r"(a[2]), "r"(a[3]), "r"(b0), "r"(b1));
}
__device__ __forceinline__ uint32_t pack_bf2(__nv_bfloat16 a, __nv_bfloat16 b) {
    return ((uint32_t)__bfloat16_as_ushort(b) << 16) | (uint32_t)__bfloat16_as_ushort(a);
}
__device__ __forceinline__ void split2(float x, float y, uint32_t& hi, uint32_t& lo) {
    __nv_bfloat16 hx = __float2bfloat16_rn(x), hy = __float2bfloat16_rn(y);
    hi = pack_bf2(hx, hy);
    lo = pack_bf2(__float2bfloat16_rn(x - __bfloat162float(hx)),
                  __float2bfloat16_rn(y - __bfloat162float(hy)));
}

// ============================================================================
// x_prep: fp32 [M][512] -> bf16 split [M][1536] = [hi, hi, lo]
// ============================================================================
__global__ __launch_bounds__(256) void x_prep(
    const float* __restrict__ src, __nv_bfloat16* __restrict__ dst)
{
    int idx = blockIdx.x * 256 + threadIdx.x;
    int row = idx >> 7, cc = (idx & 127) * 4;
    float4 v = *(const float4*)&src[(size_t)row * 512 + cc];
    uint32_t h0, l0, h1, l1;
    split2(v.x, v.y, h0, l0);
    split2(v.z, v.w, h1, l1);
    __nv_bfloat16* d = dst + (size_t)row * 1536 + cc;
    uint2 hi = {h0, h1}, lo = {l0, l1};
    *(uint2*)(d)        = hi;
    *(uint2*)(d + 512)  = hi;
    *(uint2*)(d + 1024) = lo;
}

// ============================================================================
// w_prep: W [512][512] fp32 -> g_wt[z] [n][1536] = [Whi, Wlo, Whi] transposed
// ============================================================================
__global__ __launch_bounds__(256) void w_prep(
    const float* __restrict__ Wq, const float* __restrict__ Wk,
    const float* __restrict__ Wv, const float* __restrict__ Wo)
{
    __shared__ float ts[64][65];
    const int tid = threadIdx.x, z = blockIdx.z;
    const float* W = (z == 0) ? Wq : (z == 1) ? Wk : (z == 2) ? Wv : Wo;
    const int k0 = blockIdx.x * 64, n0 = blockIdx.y * 64;
    #pragma unroll
    for (int j = 0; j < 4; j++) {
        int lin = tid + j * 256;
        int r = lin >> 4, c = (lin & 15) * 4;
        float4 v = *(const float4*)&W[(size_t)(k0 + r) * 512 + n0 + c];
        ts[r][c] = v.x; ts[r][c+1] = v.y; ts[r][c+2] = v.z; ts[r][c+3] = v.w;
    }
    __syncthreads();
    const int nn = tid >> 2, kk = (tid & 3) * 16;
    uint32_t hp[8], lp[8];
    #pragma unroll
    for (int j = 0; j < 8; j++)
        split2(ts[kk + 2*j][nn], ts[kk + 2*j + 1][nn], hp[j], lp[j]);
    __nv_bfloat16* dst = g_wt + ((size_t)z * 512 + n0 + nn) * 1536 + k0 + kk;
    uint4 h0 = {hp[0],hp[1],hp[2],hp[3]}, h1 = {hp[4],hp[5],hp[6],hp[7]};
    uint4 l0 = {lp[0],lp[1],lp[2],lp[3]}, l1 = {lp[4],lp[5],lp[6],lp[7]};
    *(uint4*)(dst)          = h0;  *(uint4*)(dst + 8)        = h1;
    *(uint4*)(dst + 512)    = l0;  *(uint4*)(dst + 512 + 8)  = l1;
    *(uint4*)(dst + 1024)   = h0;  *(uint4*)(dst + 1024 + 8) = h1;
}

// ============================================================================
// proj_mma: 256 threads, 8 warps (4x2 of 32x64 warp tiles). cp.async 2-stage.
// mode = modeBase + blockIdx.z: 0 fp32 out, 1 q-split, 2 k-split, 3 v-scatter.
// ============================================================================
#define PJ_STAGE (2*128*SPAD)
#define PJ_SMEM  (2*PJ_STAGE*2)

__global__ __launch_bounds__(256) void proj_mma(
    const __nv_bfloat16* __restrict__ A, const __nv_bfloat16* __restrict__ WtBase,
    const float* __restrict__ b0, const float* __restrict__ b1,
    const float* __restrict__ b2, const float* __restrict__ pe,
    float* __restrict__ outf, int modeBase)
{
    extern __shared__ __nv_bfloat16 sm[];
    const int tid = threadIdx.x, wid = tid >> 5, lane = tid & 31;
    const int colBase = blockIdx.x * 128, rowBase = blockIdx.y * 128;
    const int z = blockIdx.z;
    const int mode = modeBase + z;
    const __nv_bfloat16* Wt = WtBase + (size_t)z * 512 * 1536;
    const float* bias = (z == 0) ? b0 : (z == 1) ? b1 : b2;

    const uint32_t sbase = smem_u32(sm);
    const int wm = (wid & 3) * 32, wn = (wid >> 2) * 64;
    const uint32_t aOff = (((wm + (lane & 15)) * SPAD) + ((lane >> 4) * 8)) << 1;
    const int brow = (lane & 7) + ((lane >> 4) << 3);
    const int bcol = ((lane >> 3) & 1) * 8;
    const uint32_t bOff = (((128*SPAD) + (wn + brow) * SPAD) + bcol) << 1;

    auto load_stage = [&](int ck, int st) {
        const __nv_bfloat16* Ap = A  + (size_t)rowBase * 1536 + ck * 192;
        const __nv_bfloat16* Bp = Wt + (size_t)colBase * 1536 + ck * 192;
        uint32_t sa = sbase + (uint32_t)st * PJ_STAGE * 2;
        #pragma unroll
        for (int t = 0; t < 12; t++) {
            int idx = tid + t * 256;
            int row = idx / 24, cc = (idx % 24) * 8;
            cp16(sa + ((row*SPAD + cc) << 1),            Ap + (size_t)row * 1536 + cc);
            cp16(sa + ((128*SPAD + row*SPAD + cc) << 1), Bp + (size_t)row * 1536 + cc);
        }
        CP_COMMIT();
    };

    float acc[2][8][4];
    #pragma unroll
    for (int i = 0; i < 2; i++)
        #pragma unroll
        for (int j = 0; j < 8; j++)
            #pragma unroll
            for (int k = 0; k < 4; k++) acc[i][j][k] = 0.f;

    load_stage(0, 0);
    load_stage(1, 1);

    for (int ck = 0; ck < 8; ck++) {
        const int st = ck & 1;
        if (ck < 6) { CP_WAIT1(); } else { CP_WAIT0(); }
        __syncthreads();
        const uint32_t stageB = sbase + (uint32_t)st * PJ_STAGE * 2;
        #pragma unroll
        for (int k0 = 0; k0 < 192; k0 += 16) {
            uint32_t a[2][4], bb[4][4];
            ldm4(a[0], stageB + aOff + (k0 << 1));
            ldm4(a[1], stageB + aOff + ((16*SPAD + k0) << 1));
            #pragma unroll
            for (int p = 0; p < 4; p++) ldm4(bb[p], stageB + bOff + ((p*16*SPAD + k0) << 1));
            #pragma unroll
            for (int mt = 0; mt < 2; mt++)
                #pragma unroll
                for (int nt = 0; nt < 8; nt++)
                    mma16816(acc[mt][nt], a[mt], bb[nt>>1][(nt&1)*2], bb[nt>>1][(nt&1)*2+1]);
        }
        __syncthreads();
        if (ck + 2 < 8) load_stage(ck + 2, st);
    }

    const int g = lane >> 2, tg = lane & 3;
    #pragma unroll
    for (int mt = 0; mt < 2; mt++) {
        #pragma unroll
        for (int nt = 0; nt < 8; nt++) {
            int c = colBase + wn + nt*8 + tg*2;
            float bx = bias[c], by = bias[c+1];
            int h = c >> 6, d = c & 63;
            #pragma unroll
            for (int half = 0; half < 2; half++) {
                int r = rowBase + wm + mt*16 + g + half*8;
                int bb2 = r >> 11, s = r & 2047;
                float vx = acc[mt][nt][half*2]     + bx;
                float vy = acc[mt][nt][half*2 + 1] + by;
                if (mode == 0) {
                    float2 o = {vx, vy};
                    *(float2*)&outf[(size_t)r * 512 + c] = o;
                } else if (mode == 3) {
                    float2 o = {vx, vy};
                    *(float2*)&g_v[(((size_t)bb2 * H_ + h) * S_ + s) * HD + d] = o;
                } else {
                    float2 p = *(const float2*)&pe[(size_t)s * DH + c];
                    vx += p.x; vy += p.y;
                    uint32_t hi, lo;
                    split2(vx, vy, hi, lo);
                    __nv_bfloat16* base = (mode == 1 ? g_qs : g_ks)
                        + ((size_t)(bb2 * H_ + h) * S_ + s) * 192 + d;
                    if (mode == 1) {
                        *(uint32_t*)(base) = hi; *(uint32_t*)(base+64) = hi; *(uint32_t*)(base+128) = lo;
                    } else {
                        *(uint32_t*)(base) = hi; *(uint32_t*)(base+64) = lo; *(uint32_t*)(base+128) = hi;
                    }
                }
            }
        }
    }
}

// ============================================================================
// v_prep: g_v [bh][s][64] -> g_vt [bh][d][6144]; per 64-chunk: [Vhi,Vlo,Vhi]
// ============================================================================
__global__ __launch_bounds__(256) void v_prep()
{
    __shared__ float ts[64][65];
    const int tid = threadIdx.x, ch = blockIdx.x, bh = blockIdx.y;
    const float* vsrc = g_v + ((size_t)bh * S_ + ch * 64) * HD;
    #pragma unroll
    for (int j = 0; j < 4; j++) {
        int lin = tid + j * 256;
        int r = lin >> 4, cc = (lin & 15) * 4;
        float4 v = *(const float4*)(vsrc + (size_t)r * HD + cc);
        ts[r][cc] = v.x; ts[r][cc+1] = v.y; ts[r][cc+2] = v.z; ts[r][cc+3] = v.w;
    }
    __syncthreads();
    const int n = tid & 63, rg = (tid >> 6) * 16;
    uint32_t hp[8], lp[8];
    #pragma unroll
    for (int q = 0; q < 8; q++)
        split2(ts[rg + 2*q][n], ts[rg + 2*q + 1][n], hp[q], lp[q]);
    __nv_bfloat16* dst = g_vt + ((size_t)bh * HD + n) * 6144 + (size_t)ch * 192;
    uint4 h0 = {hp[0],hp[1],hp[2],hp[3]}, h1 = {hp[4],hp[5],hp[6],hp[7]};
    uint4 l0 = {lp[0],lp[1],lp[2],lp[3]}, l1 = {lp[4],lp[5],lp[6],lp[7]};
    *(uint4*)(dst + rg)        = h0;  *(uint4*)(dst + rg + 8)       = h1;
    *(uint4*)(dst + 64 + rg)   = l0;  *(uint4*)(dst + 64 + rg + 8)  = l1;
    *(uint4*)(dst + 128 + rg)  = h0;  *(uint4*)(dst + 128 + rg + 8) = h1;
}

// ============================================================================
// scores_mma: 256 threads, 8 warps (4x2 of 32x64 warp tiles). Writes masked
// scaled raw scores AND per-warp row softmax partials (max, expsum).
// ============================================================================
#define SC_SMEM (2*128*SPAD*2)

__global__ __launch_bounds__(256) void scores_mma(
    const int* __restrict__ mask, float* __restrict__ attn)
{
    extern __shared__ __nv_bfloat16 sm[];
    __nv_bfloat16* sA = sm;
    __nv_bfloat16* sB = sm + 128*SPAD;
    const int tid = threadIdx.x, wid = tid >> 5, lane = tid & 31;
    const int nBase = blockIdx.x * 128, mBase = blockIdx.y * 128, bh = blockIdx.z;
    const int b = bh >> 3;

    const __nv_bfloat16* qs = g_qs + ((size_t)bh * S_ + mBase) * 192;
    const __nv_bfloat16* ks = g_ks + ((size_t)bh * S_ + nBase) * 192;
    #pragma unroll
    for (int t = 0; t < 12; t++) {
        int idx = tid + t * 256;
        int row = idx / 24, cc = (idx % 24) * 8;
        cp16(smem_u32(&sA[row*SPAD + cc]), qs + (size_t)row * 192 + cc);
        cp16(smem_u32(&sB[row*SPAD + cc]), ks + (size_t)row * 192 + cc);
    }
    CP_COMMIT();
    CP_WAIT0();
    __syncthreads();

    const int wm = (wid & 3) * 32, wn = (wid >> 2) * 64;
    uint32_t aBase = smem_u32(sA) + ((((wm + (lane & 15)) * SPAD) + ((lane >> 4) * 8)) << 1);
    const int brow = (lane & 7) + ((lane >> 4) << 3);
    const int bcol = ((lane >> 3) & 1) * 8;
    uint32_t bBase = smem_u32(sB) + ((((wn + brow) * SPAD) + bcol) << 1);

    float acc[2][8][4];
    #pragma unroll
    for (int i = 0; i < 2; i++)
        #pragma unroll
        for (int j = 0; j < 8; j++)
            #pragma unroll
            for (int k = 0; k < 4; k++) acc[i][j][k] = 0.f;

    #pragma unroll
    for (int k0 = 0; k0 < 192; k0 += 16) {
        uint32_t a[2][4], bb[4][4];
        ldm4(a[0], aBase + (k0 << 1));
        ldm4(a[1], aBase + ((16*SPAD + k0) << 1));
        #pragma unroll
        for (int p = 0; p < 4; p++) ldm4(bb[p], bBase + ((p*16*SPAD + k0) << 1));
        #pragma unroll
        for (int mt = 0; mt < 2; mt++)
            #pragma unroll
            for (int nt = 0; nt < 8; nt++)
                mma16816(acc[mt][nt], a[mt], bb[nt>>1][(nt&1)*2], bb[nt>>1][(nt&1)*2+1]);
    }

    const int g = lane >> 2, tg = lane & 3;
    // write masked scaled scores; keep masked values back in acc for stats
    #pragma unroll
    for (int mt = 0; mt < 2; mt++) {
        #pragma unroll
        for (int nt = 0; nt < 8; nt++) {
            int col = nBase + wn + nt*8 + tg*2;
            int r0 = mBase + wm + mt*16 + g;
            int2 m0 = *(const int2*)&mask[((size_t)b * S_ + r0) * S_ + col];
            float2 o0;
            o0.x = m0.x ? acc[mt][nt][0]*0.125f : -FLT_MAX;
            o0.y = m0.y ? acc[mt][nt][1]*0.125f : -FLT_MAX;
            *(float2*)&attn[((size_t)bh * S_ + r0) * S_ + col] = o0;
            acc[mt][nt][0] = o0.x; acc[mt][nt][1] = o0.y;
            int r1 = r0 + 8;
            int2 m1 = *(const int2*)&mask[((size_t)b * S_ + r1) * S_ + col];
            float2 o1;
            o1.x = m1.x ? acc[mt][nt][2]*0.125f : -FLT_MAX;
            o1.y = m1.y ? acc[mt][nt][3]*0.125f : -FLT_MAX;
            *(float2*)&attn[((size_t)bh * S_ + r1) * S_ + col] = o1;
            acc[mt][nt][2] = o1.x; acc[mt][nt][3] = o1.y;
        }
    }
    // per-row partial stats over this warp's 64 cols (4 tg-lanes share a row)
    #pragma unroll
    for (int mt = 0; mt < 2; mt++) {
        #pragma unroll
        for (int half = 0; half < 2; half++) {
            float mx = -FLT_MAX;
            #pragma unroll
            for (int nt = 0; nt < 8; nt++)
                mx = fmaxf(mx, fmaxf(acc[mt][nt][half*2], acc[mt][nt][half*2+1]));
            mx = fmaxf(mx, __shfl_xor_sync(~0u, mx, 1));
            mx = fmaxf(mx, __shfl_xor_sync(~0u, mx, 2));
            float sum = 0.f;
            #pragma unroll
            for (int nt = 0; nt < 8; nt++) {
                sum += __expf(acc[mt][nt][half*2]   - mx);
                sum += __expf(acc[mt][nt][half*2+1] - mx);
            }
            sum += __shfl_xor_sync(~0u, sum, 1);
            sum += __shfl_xor_sync(~0u, sum, 2);
            if (tg == 0) {
                int r = mBase + wm + mt*16 + g + half*8;
                g_part[((size_t)bh * S_ + r) * 32 + blockIdx.x * 2 + (wid >> 2)]
                    = make_float2(mx, sum);
            }
        }
    }
}

// ============================================================================
// reduce_stats: one warp per row; combine 32 partials -> (max, 1/sum)
// ============================================================================
__global__ __launch_bounds__(256) void reduce_stats()
{
    const int row = blockIdx.x * 8 + (threadIdx.x >> 5);
    const int lane = threadIdx.x & 31;
    float2 p = g_part[(size_t)row * 32 + lane];
    float M = p.x;
    #pragma unroll
    for (int o = 16; o > 0; o >>= 1) M = fmaxf(M, __shfl_xor_sync(~0u, M, o));
    float s = __expf(p.x - M) * p.y;
    #pragma unroll
    for (int o = 16; o > 0; o >>= 1) s += __shfl_xor_sync(~0u, s, o);
    if (lane == 0) g_stats[row] = make_float2(M, 1.f / s);
}

// ============================================================================
// pv_mma: 256 threads, 8 warps of 16x64 tiles. Reads raw scores, applies
// p = exp(s - mx) * inv, writes final P to attn (output), PV via split-bf16.
// ============================================================================
#define PV_SMEM ((128*SPAD + 64*SPAD)*2 + 128*8)

__global__ __launch_bounds__(256) void pv_mma(float* __restrict__ attn)
{
    extern __shared__ __nv_bfloat16 sm[];
    __nv_bfloat16* sA = sm;
    __nv_bfloat16* sB = sm + 128*SPAD;
    float2* sStat = (float2*)(sm + 128*SPAD + 64*SPAD);
    const int tid = threadIdx.x, wid = tid >> 5, lane = tid & 31;
    const int mBase = blockIdx.x * 128, bh = blockIdx.y;
    const int b = bh >> 3, h = bh & 7;

    float* prow = attn + ((size_t)bh * S_ + mBase) * S_;
    const __nv_bfloat16* vt = g_vt + (size_t)bh * HD * 6144;

    if (tid < 128) sStat[tid] = g_stats[(size_t)bh * S_ + mBase + tid];

    const int wm = wid * 16;
    uint32_t aBase = smem_u32(sA) + ((((wm + (lane & 15)) * SPAD) + ((lane >> 4) * 8)) << 1);
    const int brow = (lane & 7) + ((lane >> 4) << 3);
    const int bcol = ((lane >> 3) & 1) * 8;
    uint32_t bBase = smem_u32(sB) + (((brow * SPAD) + bcol) << 1);

    float acc[8][4];
    #pragma unroll
    for (int j = 0; j < 8; j++)
        #pragma unroll
        for (int k = 0; k < 4; k++) acc[j][k] = 0.f;

    for (int ch = 0; ch < 32; ch++) {
        __syncthreads();
        #pragma unroll
        for (int j = 0; j < 6; j++) {
            int idx = tid + j * 256;
            int n = idx / 24, cc = (idx % 24) * 8;
            cp16(smem_u32(&sB[n*SPAD + cc]), vt + (size_t)n * 6144 + (size_t)ch * 192 + cc);
        }
        CP_COMMIT();
        const int s0 = ch * 64;
        #pragma unroll
        for (int j = 0; j < 8; j++) {
            int lin = tid + j * 256;
            int row = lin >> 4, l = (lin & 15) * 4;
            float4 p = *(const float4*)(prow + (size_t)row * S_ + s0 + l);
            float2 st = sStat[row];
            float4 q;
            q.x = __expf(p.x - st.x) * st.y;
            q.y = __expf(p.y - st.x) * st.y;
            q.z = __expf(p.z - st.x) * st.y;
            q.w = __expf(p.w - st.x) * st.y;
            *(float4*)(prow + (size_t)row * S_ + s0 + l) = q;   // final P output
            uint32_t h0, l0, h1, l1;
            split2(q.x, q.y, h0, l0);
            split2(q.z, q.w, h1, l1);
            uint2 hi = {h0, h1}, lo = {l0, l1};
            *(uint2*)&sA[row*SPAD + l]       = hi;
            *(uint2*)&sA[row*SPAD + 64 + l]  = hi;
            *(uint2*)&sA[row*SPAD + 128 + l] = lo;
        }
        CP_WAIT0();
        __syncthreads();
        #pragma unroll
        for (int k0 = 0; k0 < 192; k0 += 16) {
            uint32_t a[4], bb[4][4];
            ldm4(a, aBase + (k0 << 1));
            #pragma unroll
            for (int p = 0; p < 4; p++) ldm4(bb[p], bBase + ((p*16*SPAD + k0) << 1));
            #pragma unroll
            for (int nt = 0; nt < 8; nt++)
                mma16816(acc[nt], a, bb[nt>>1][(nt&1)*2], bb[nt>>1][(nt&1)*2+1]);
        }
    }

    const int g = lane >> 2, tg = lane & 3;
    #pragma unroll
    for (int nt = 0; nt < 8; nt++) {
        int col = h * 64 + nt*8 + tg*2;
        int r0 = mBase + wm + g;
        float2 o0 = {acc[nt][0], acc[nt][1]};
        float2 o1 = {acc[nt][2], acc[nt][3]};
        *(float2*)&g_ao[((size_t)b * S_ + r0) * DH + col] = o0;
        *(float2*)&g_ao[((size_t)b * S_ + r0 + 8) * DH + col] = o1;
    }
}

// ============================================================================
// LayerNorm (512) per row.
// ============================================================================
__global__ __launch_bounds__(128) void ln_kernel(
    const float* __restrict__ gamma, const float* __restrict__ beta,
    float* __restrict__ out)
{
    __shared__ float red[8];
    const int r = blockIdx.x, tid = threadIdx.x;
    float4 v = *(const float4*)&g_o[(size_t)r * 512 + tid * 4];
    float s  = v.x + v.y + v.z + v.w;
    float sq = v.x*v.x + v.y*v.y + v.z*v.z + v.w*v.w;
    #pragma unroll
    for (int o = 16; o > 0; o >>= 1) {
        s  += __shfl_xor_sync(~0u, s,  o);
        sq += __shfl_xor_sync(~0u, sq, o);
    }
    if ((tid & 31) == 0) { red[tid >> 5] = s; red[4 + (tid >> 5)] = sq; }
    __syncthreads();
    if (tid < 32) {
        float a  = (tid < 4) ? red[tid]     : 0.f;
        float b2 = (tid < 4) ? red[4 + tid] : 0.f;
        #pragma unroll
        for (int o = 2; o > 0; o >>= 1) {
            a  += __shfl_xor_sync(~0u, a,  o);
            b2 += __shfl_xor_sync(~0u, b2, o);
        }
        if (tid == 0) { red[0] = a; red[1] = b2; }
    }
    __syncthreads();
    float mean = red[0] * (1.f / 512.f);
    float var  = red[1] * (1.f / 512.f) - mean * mean;
    float inv  = rsqrtf(var + 1e-5f);
    int c = tid * 4;
    float4 g4 = *(const float4*)&gamma[c];
    float4 b4 = *(const float4*)&beta[c];
    float4 o4;
    o4.x = (v.x - mean) * inv * g4.x + b4.x;
    o4.y = (v.y - mean) * inv * g4.y + b4.y;
    o4.z = (v.z - mean) * inv * g4.z + b4.z;
    o4.w = (v.w - mean) * inv * g4.w + b4.w;
    *(float4*)&out[(size_t)r * 512 + c] = o4;
}

// ============================================================================
extern "C" void kernel_launch(void* const* d_in, const int* in_sizes, int n_in,
                              void* d_out, int out_size)
{
    const float* x    = (const float*)d_in[0];
    const int*   mask = (const int*)  d_in[1];
    const float* Wq   = (const float*)d_in[2];
    const float* bq   = (const float*)d_in[3];
    const float* Wk   = (const float*)d_in[4];
    const float* bk   = (const float*)d_in[5];
    const float* Wv   = (const float*)d_in[6];
    const float* bv   = (const float*)d_in[7];
    const float* pe   = (const float*)d_in[8];
    const float* Wo   = (const float*)d_in[9];
    const float* bo   = (const float*)d_in[10];
    const float* gam  = (const float*)d_in[11];
    const float* bet  = (const float*)d_in[12];
    float* out = (float*)d_out;

    float *aop, *op, *fb;
    __nv_bfloat16 *xsp, *aosp, *wtp;
    cudaGetSymbolAddress((void**)&aop,  g_ao);
    cudaGetSymbolAddress((void**)&op,   g_o);
    cudaGetSymbolAddress((void**)&fb,   g_attn_fb);
    cudaGetSymbolAddress((void**)&xsp,  g_xs);
    cudaGetSymbolAddress((void**)&aosp, g_aos);
    cudaGetSymbolAddress((void**)&wtp,  g_wt);

    const size_t out_elems  = (size_t)M_ * DH;
    const size_t attn_elems = (size_t)BH_ * S_ * S_;
    int write_attn = ((size_t)out_size >= out_elems + attn_elems) ? 1 : 0;
    float* attn_buf = write_attn ? (out + out_elems) : fb;

    cudaFuncSetAttribute(scores_mma, cudaFuncAttributeMaxDynamicSharedMemorySize, SC_SMEM);
    cudaFuncSetAttribute(pv_mma,     cudaFuncAttributeMaxDynamicSharedMemorySize, PV_SMEM);
    cudaFuncSetAttribute(proj_mma,   cudaFuncAttributeMaxDynamicSharedMemorySize, PJ_SMEM);

    x_prep<<<M_*128/256, 256>>>(x, xsp);
    w_prep<<<dim3(8, 8, 4), 256>>>(Wq, Wk, Wv, Wo);

    // fused QKV: z=0 -> Q (mode 1), z=1 -> K (mode 2), z=2 -> V (mode 3)
    proj_mma<<<dim3(4, 64, 3), 256, PJ_SMEM>>>(xsp, wtp, bq, bk, bv, pe, nullptr, 1);
    v_prep<<<dim3(32, 32), 256>>>();

    scores_mma<<<dim3(16, 16, 32), 256, SC_SMEM>>>(mask, attn_buf);
    reduce_stats<<<BH_*S_/8, 256>>>();
    pv_mma<<<dim3(16, 32), 256, PV_SMEM>>>(attn_buf);

    x_prep<<<M_*128/256, 256>>>(aop, aosp);
    proj_mma<<<dim3(4, 64, 1), 256, PJ_SMEM>>>(aosp, wtp + (size_t)3*512*1536,
                                               bo, bo, bo, nullptr, op, 0);
    ln_kernel<<<M_, 128>>>(gam, bet, out);
}

// round 14
// speedup vs baseline: 1.2039x; 1.1480x over previous
#include <cuda_runtime.h>
#include <cuda_bf16.h>
#include <math.h>
#include <float.h>
#include <stdint.h>

#define B_   4
#define S_   2048
#define DH   512
#define H_   8
#define HD   64
#define M_   (B_*S_)
#define BH_  (B_*H_)
#define SPAD 200   // padded smem row stride (elems); 400B -> ldmatrix conflict-free

// -------- scratch --------
__device__ float g_v [BH_*S_*HD];
__device__ float g_ao[M_*DH];
__device__ float g_o [M_*DH];
__device__ float g_attn_fb[(size_t)BH_*S_*S_];
__device__ __align__(16) __nv_bfloat16 g_qs[(size_t)BH_*S_*192];   // [Qhi,Qhi,Qlo]
__device__ __align__(16) __nv_bfloat16 g_ks[(size_t)BH_*S_*192];   // [Khi,Klo,Khi]
__device__ __align__(16) __nv_bfloat16 g_vt[(size_t)BH_*HD*6144];  // V^T split per 64-chunk
__device__ __align__(16) __nv_bfloat16 g_xs [(size_t)M_*1536];     // X  split [hi,hi,lo]
__device__ __align__(16) __nv_bfloat16 g_aos[(size_t)M_*1536];     // AO split [hi,hi,lo]
__device__ __align__(16) __nv_bfloat16 g_wt [(size_t)4*512*1536];  // W^T split [hi,lo,hi]

// ---------------- helpers ----------------
__device__ __forceinline__ uint32_t smem_u32(const void* p) {
    uint32_t a;
    asm("{ .reg .u64 t; cvta.to.shared.u64 t, %1; cvt.u32.u64 %0, t; }" : "=r"(a) : "l"(p));
    return a;
}
__device__ __forceinline__ void cp16(uint32_t s, const void* g) {
    asm volatile("cp.async.cg.shared.global [%0], [%1], 16;" :: "r"(s), "l"(g) : "memory");
}
#define CP_COMMIT() asm volatile("cp.async.commit_group;" ::: "memory")
#define CP_WAIT0()  asm volatile("cp.async.wait_group 0;" ::: "memory")
__device__ __forceinline__ void ldm4(uint32_t* r, uint32_t addr) {
    asm volatile("ldmatrix.sync.aligned.m8n8.x4.shared.b16 {%0,%1,%2,%3}, [%4];"
        : "=r"(r[0]), "=r"(r[1]), "=r"(r[2]), "=r"(r[3]) : "r"(addr));
}
__device__ __forceinline__ void mma16816(float* d, const uint32_t* a, uint32_t b0, uint32_t b1) {
    asm volatile("mma.sync.aligned.m16n8k16.row.col.f32.bf16.bf16.f32 "
        "{%0,%1,%2,%3}, {%4,%5,%6,%7}, {%8,%9}, {%0,%1,%2,%3};"
        : "+f"(d[0]), "+f"(d[1]), "+f"(d[2]), "+f"(d[3])
        : "r"(a[0]), "r"(a[1]), "r"(a[2]), "r"(a[3]), "r"(b0), "r"(b1));
}
__device__ __forceinline__ uint32_t pack_bf2(__nv_bfloat16 a, __nv_bfloat16 b) {
    return ((uint32_t)__bfloat16_as_ushort(b) << 16) | (uint32_t)__bfloat16_as_ushort(a);
}
__device__ __forceinline__ void split2(float x, float y, uint32_t& hi, uint32_t& lo) {
    __nv_bfloat16 hx = __float2bfloat16_rn(x), hy = __float2bfloat16_rn(y);
    hi = pack_bf2(hx, hy);
    lo = pack_bf2(__float2bfloat16_rn(x - __bfloat162float(hx)),
                  __float2bfloat16_rn(y - __bfloat162float(hy)));
}

// ============================================================================
// x_prep: fp32 [M][512] -> bf16 split [M][1536] = [hi, hi, lo]
// ============================================================================
__global__ __launch_bounds__(256) void x_prep(
    const float* __restrict__ src, __nv_bfloat16* __restrict__ dst)
{
    int idx = blockIdx.x * 256 + threadIdx.x;
    int row = idx >> 7, cc = (idx & 127) * 4;
    float4 v = *(const float4*)&src[(size_t)row * 512 + cc];
    uint32_t h0, l0, h1, l1;
    split2(v.x, v.y, h0, l0);
    split2(v.z, v.w, h1, l1);
    __nv_bfloat16* d = dst + (size_t)row * 1536 + cc;
    uint2 hi = {h0, h1}, lo = {l0, l1};
    *(uint2*)(d)        = hi;
    *(uint2*)(d + 512)  = hi;
    *(uint2*)(d + 1024) = lo;
}

// ============================================================================
// w_prep: W [512][512] fp32 -> g_wt[z] [n][1536] = [Whi, Wlo, Whi] transposed
// ============================================================================
__global__ __launch_bounds__(256) void w_prep(
    const float* __restrict__ Wq, const float* __restrict__ Wk,
    const float* __restrict__ Wv, const float* __restrict__ Wo)
{
    __shared__ float ts[64][65];
    const int tid = threadIdx.x, z = blockIdx.z;
    const float* W = (z == 0) ? Wq : (z == 1) ? Wk : (z == 2) ? Wv : Wo;
    const int k0 = blockIdx.x * 64, n0 = blockIdx.y * 64;
    #pragma unroll
    for (int j = 0; j < 4; j++) {
        int lin = tid + j * 256;
        int r = lin >> 4, c = (lin & 15) * 4;
        float4 v = *(const float4*)&W[(size_t)(k0 + r) * 512 + n0 + c];
        ts[r][c] = v.x; ts[r][c+1] = v.y; ts[r][c+2] = v.z; ts[r][c+3] = v.w;
    }
    __syncthreads();
    const int nn = tid >> 2, kk = (tid & 3) * 16;
    uint32_t hp[8], lp[8];
    #pragma unroll
    for (int j = 0; j < 8; j++)
        split2(ts[kk + 2*j][nn], ts[kk + 2*j + 1][nn], hp[j], lp[j]);
    __nv_bfloat16* dst = g_wt + ((size_t)z * 512 + n0 + nn) * 1536 + k0 + kk;
    uint4 h0 = {hp[0],hp[1],hp[2],hp[3]}, h1 = {hp[4],hp[5],hp[6],hp[7]};
    uint4 l0 = {lp[0],lp[1],lp[2],lp[3]}, l1 = {lp[4],lp[5],lp[6],lp[7]};
    *(uint4*)(dst)          = h0;  *(uint4*)(dst + 8)        = h1;
    *(uint4*)(dst + 512)    = l0;  *(uint4*)(dst + 512 + 8)  = l1;
    *(uint4*)(dst + 1024)   = h0;  *(uint4*)(dst + 1024 + 8) = h1;
}

// ============================================================================
// proj_mma: 256 threads, 8 warps (4x2 of 32x64 warp tiles), single-stage
// loads, __launch_bounds__(256,2) for 2 CTAs/SM (cross-CTA overlap).
// mode = modeBase + blockIdx.z: 0 fp32 out, 1 q-split, 2 k-split, 3 v-scatter.
// ============================================================================
#define PJ_SMEM (2*128*SPAD*2)

__global__ __launch_bounds__(256, 2) void proj_mma(
    const __nv_bfloat16* __restrict__ A, const __nv_bfloat16* __restrict__ WtBase,
    const float* __restrict__ b0, const float* __restrict__ b1,
    const float* __restrict__ b2, const float* __restrict__ pe,
    float* __restrict__ outf, int modeBase)
{
    extern __shared__ __nv_bfloat16 sm[];
    __nv_bfloat16* sA = sm;
    __nv_bfloat16* sB = sm + 128*SPAD;
    const int tid = threadIdx.x, wid = tid >> 5, lane = tid & 31;
    const int colBase = blockIdx.x * 128, rowBase = blockIdx.y * 128;
    const int z = blockIdx.z;
    const int mode = modeBase + z;
    const __nv_bfloat16* Wt = WtBase + (size_t)z * 512 * 1536;
    const float* bias = (z == 0) ? b0 : (z == 1) ? b1 : b2;

    const int wm = (wid & 3) * 32, wn = (wid >> 2) * 64;
    uint32_t aBase = smem_u32(sA) + ((((wm + (lane & 15)) * SPAD) + ((lane >> 4) * 8)) << 1);
    const int brow = (lane & 7) + ((lane >> 4) << 3);
    const int bcol = ((lane >> 3) & 1) * 8;
    uint32_t bBase = smem_u32(sB) + ((((wn + brow) * SPAD) + bcol) << 1);

    float acc[2][8][4];
    #pragma unroll
    for (int i = 0; i < 2; i++)
        #pragma unroll
        for (int j = 0; j < 8; j++)
            #pragma unroll
            for (int k = 0; k < 4; k++) acc[i][j][k] = 0.f;

    for (int ck = 0; ck < 8; ck++) {
        __syncthreads();
        const __nv_bfloat16* Ap = A  + (size_t)rowBase * 1536 + ck * 192;
        const __nv_bfloat16* Bp = Wt + (size_t)colBase * 1536 + ck * 192;
        #pragma unroll
        for (int t = 0; t < 12; t++) {
            int idx = tid + t * 256;
            int row = idx / 24, cc = (idx % 24) * 8;
            cp16(smem_u32(&sA[row*SPAD + cc]), Ap + (size_t)row * 1536 + cc);
            cp16(smem_u32(&sB[row*SPAD + cc]), Bp + (size_t)row * 1536 + cc);
        }
        CP_COMMIT();
        CP_WAIT0();
        __syncthreads();
        #pragma unroll
        for (int k0 = 0; k0 < 192; k0 += 16) {
            uint32_t a[2][4], bb[4][4];
            ldm4(a[0], aBase + (k0 << 1));
            ldm4(a[1], aBase + ((16*SPAD + k0) << 1));
            #pragma unroll
            for (int p = 0; p < 4; p++) ldm4(bb[p], bBase + ((p*16*SPAD + k0) << 1));
            #pragma unroll
            for (int mt = 0; mt < 2; mt++)
                #pragma unroll
                for (int nt = 0; nt < 8; nt++)
                    mma16816(acc[mt][nt], a[mt], bb[nt>>1][(nt&1)*2], bb[nt>>1][(nt&1)*2+1]);
        }
    }

    const int g = lane >> 2, tg = lane & 3;
    #pragma unroll
    for (int mt = 0; mt < 2; mt++) {
        #pragma unroll
        for (int nt = 0; nt < 8; nt++) {
            int c = colBase + wn + nt*8 + tg*2;
            float bx = bias[c], by = bias[c+1];
            int h = c >> 6, d = c & 63;
            #pragma unroll
            for (int half = 0; half < 2; half++) {
                int r = rowBase + wm + mt*16 + g + half*8;
                int bb2 = r >> 11, s = r & 2047;
                float vx = acc[mt][nt][half*2]     + bx;
                float vy = acc[mt][nt][half*2 + 1] + by;
                if (mode == 0) {
                    float2 o = {vx, vy};
                    *(float2*)&outf[(size_t)r * 512 + c] = o;
                } else if (mode == 3) {
                    float2 o = {vx, vy};
                    *(float2*)&g_v[(((size_t)bb2 * H_ + h) * S_ + s) * HD + d] = o;
                } else {
                    float2 p = *(const float2*)&pe[(size_t)s * DH + c];
                    vx += p.x; vy += p.y;
                    uint32_t hi, lo;
                    split2(vx, vy, hi, lo);
                    __nv_bfloat16* base = (mode == 1 ? g_qs : g_ks)
                        + ((size_t)(bb2 * H_ + h) * S_ + s) * 192 + d;
                    if (mode == 1) {
                        *(uint32_t*)(base) = hi; *(uint32_t*)(base+64) = hi; *(uint32_t*)(base+128) = lo;
                    } else {
                        *(uint32_t*)(base) = hi; *(uint32_t*)(base+64) = lo; *(uint32_t*)(base+128) = hi;
                    }
                }
            }
        }
    }
}

// ============================================================================
// v_prep: g_v [bh][s][64] -> g_vt [bh][d][6144]; per 64-chunk: [Vhi,Vlo,Vhi]
// ============================================================================
__global__ __launch_bounds__(256) void v_prep()
{
    __shared__ float ts[64][65];
    const int tid = threadIdx.x, ch = blockIdx.x, bh = blockIdx.y;
    const float* vsrc = g_v + ((size_t)bh * S_ + ch * 64) * HD;
    #pragma unroll
    for (int j = 0; j < 4; j++) {
        int lin = tid + j * 256;
        int r = lin >> 4, cc = (lin & 15) * 4;
        float4 v = *(const float4*)(vsrc + (size_t)r * HD + cc);
        ts[r][cc] = v.x; ts[r][cc+1] = v.y; ts[r][cc+2] = v.z; ts[r][cc+3] = v.w;
    }
    __syncthreads();
    const int n = tid & 63, rg = (tid >> 6) * 16;
    uint32_t hp[8], lp[8];
    #pragma unroll
    for (int q = 0; q < 8; q++)
        split2(ts[rg + 2*q][n], ts[rg + 2*q + 1][n], hp[q], lp[q]);
    __nv_bfloat16* dst = g_vt + ((size_t)bh * HD + n) * 6144 + (size_t)ch * 192;
    uint4 h0 = {hp[0],hp[1],hp[2],hp[3]}, h1 = {hp[4],hp[5],hp[6],hp[7]};
    uint4 l0 = {lp[0],lp[1],lp[2],lp[3]}, l1 = {lp[4],lp[5],lp[6],lp[7]};
    *(uint4*)(dst + rg)        = h0;  *(uint4*)(dst + rg + 8)       = h1;
    *(uint4*)(dst + 64 + rg)   = l0;  *(uint4*)(dst + 64 + rg + 8)  = l1;
    *(uint4*)(dst + 128 + rg)  = h0;  *(uint4*)(dst + 128 + rg + 8) = h1;
}

// ============================================================================
// scores_mma: 256 threads, 8 warps (4x2 of 32x64 warp tiles), 2 CTAs/SM.
// 128x128 tile/CTA, split-bf16 K'=192.
// ============================================================================
#define SC_SMEM (2*128*SPAD*2)

__global__ __launch_bounds__(256, 2) void scores_mma(
    const int* __restrict__ mask, float* __restrict__ attn)
{
    extern __shared__ __nv_bfloat16 sm[];
    __nv_bfloat16* sA = sm;
    __nv_bfloat16* sB = sm + 128*SPAD;
    const int tid = threadIdx.x, wid = tid >> 5, lane = tid & 31;
    const int nBase = blockIdx.x * 128, mBase = blockIdx.y * 128, bh = blockIdx.z;
    const int b = bh >> 3;

    const __nv_bfloat16* qs = g_qs + ((size_t)bh * S_ + mBase) * 192;
    const __nv_bfloat16* ks = g_ks + ((size_t)bh * S_ + nBase) * 192;
    #pragma unroll
    for (int t = 0; t < 12; t++) {
        int idx = tid + t * 256;
        int row = idx / 24, cc = (idx % 24) * 8;
        cp16(smem_u32(&sA[row*SPAD + cc]), qs + (size_t)row * 192 + cc);
        cp16(smem_u32(&sB[row*SPAD + cc]), ks + (size_t)row * 192 + cc);
    }
    CP_COMMIT();
    CP_WAIT0();
    __syncthreads();

    const int wm = (wid & 3) * 32, wn = (wid >> 2) * 64;
    uint32_t aBase = smem_u32(sA) + ((((wm + (lane & 15)) * SPAD) + ((lane >> 4) * 8)) << 1);
    const int brow = (lane & 7) + ((lane >> 4) << 3);
    const int bcol = ((lane >> 3) & 1) * 8;
    uint32_t bBase = smem_u32(sB) + ((((wn + brow) * SPAD) + bcol) << 1);

    float acc[2][8][4];
    #pragma unroll
    for (int i = 0; i < 2; i++)
        #pragma unroll
        for (int j = 0; j < 8; j++)
            #pragma unroll
            for (int k = 0; k < 4; k++) acc[i][j][k] = 0.f;

    #pragma unroll
    for (int k0 = 0; k0 < 192; k0 += 16) {
        uint32_t a[2][4], bb[4][4];
        ldm4(a[0], aBase + (k0 << 1));
        ldm4(a[1], aBase + ((16*SPAD + k0) << 1));
        #pragma unroll
        for (int p = 0; p < 4; p++) ldm4(bb[p], bBase + ((p*16*SPAD + k0) << 1));
        #pragma unroll
        for (int mt = 0; mt < 2; mt++)
            #pragma unroll
            for (int nt = 0; nt < 8; nt++)
                mma16816(acc[mt][nt], a[mt], bb[nt>>1][(nt&1)*2], bb[nt>>1][(nt&1)*2+1]);
    }

    const int g = lane >> 2, tg = lane & 3;
    #pragma unroll
    for (int mt = 0; mt < 2; mt++) {
        #pragma unroll
        for (int nt = 0; nt < 8; nt++) {
            int col = nBase + wn + nt*8 + tg*2;
            int r0 = mBase + wm + mt*16 + g;
            int2 m0 = *(const int2*)&mask[((size_t)b * S_ + r0) * S_ + col];
            float2 o0;
            o0.x = m0.x ? acc[mt][nt][0]*0.125f : -FLT_MAX;
            o0.y = m0.y ? acc[mt][nt][1]*0.125f : -FLT_MAX;
            *(float2*)&attn[((size_t)bh * S_ + r0) * S_ + col] = o0;
            int r1 = r0 + 8;
            int2 m1 = *(const int2*)&mask[((size_t)b * S_ + r1) * S_ + col];
            float2 o1;
            o1.x = m1.x ? acc[mt][nt][2]*0.125f : -FLT_MAX;
            o1.y = m1.y ? acc[mt][nt][3]*0.125f : -FLT_MAX;
            *(float2*)&attn[((size_t)bh * S_ + r1) * S_ + col] = o1;
        }
    }
}

// ============================================================================
// pv_mma: 256 threads, 8 warps of 16x64 tiles, 2 CTAs/SM.
// O[128,64] = P[128,2048] @ V; 32 chunks; cp.async B overlaps P split.
// ============================================================================
#define PV_SMEM ((128*SPAD + 64*SPAD)*2)

__global__ __launch_bounds__(256, 2) void pv_mma(const float* __restrict__ attn)
{
    extern __shared__ __nv_bfloat16 sm[];
    __nv_bfloat16* sA = sm;
    __nv_bfloat16* sB = sm + 128*SPAD;
    const int tid = threadIdx.x, wid = tid >> 5, lane = tid & 31;
    const int mBase = blockIdx.x * 128, bh = blockIdx.y;
    const int b = bh >> 3, h = bh & 7;

    const float* prow = attn + ((size_t)bh * S_ + mBase) * S_;
    const __nv_bfloat16* vt = g_vt + (size_t)bh * HD * 6144;

    const int wm = wid * 16;
    uint32_t aBase = smem_u32(sA) + ((((wm + (lane & 15)) * SPAD) + ((lane >> 4) * 8)) << 1);
    const int brow = (lane & 7) + ((lane >> 4) << 3);
    const int bcol = ((lane >> 3) & 1) * 8;
    uint32_t bBase = smem_u32(sB) + (((brow * SPAD) + bcol) << 1);

    float acc[8][4];
    #pragma unroll
    for (int j = 0; j < 8; j++)
        #pragma unroll
        for (int k = 0; k < 4; k++) acc[j][k] = 0.f;

    for (int ch = 0; ch < 32; ch++) {
        __syncthreads();
        #pragma unroll
        for (int j = 0; j < 6; j++) {
            int idx = tid + j * 256;
            int n = idx / 24, cc = (idx % 24) * 8;
            cp16(smem_u32(&sB[n*SPAD + cc]), vt + (size_t)n * 6144 + (size_t)ch * 192 + cc);
        }
        CP_COMMIT();
        const int s0 = ch * 64;
        #pragma unroll
        for (int j = 0; j < 8; j++) {
            int lin = tid + j * 256;
            int row = lin >> 4, l = (lin & 15) * 4;
            float4 p = *(const float4*)(prow + (size_t)row * S_ + s0 + l);
            uint32_t h0, l0, h1, l1;
            split2(p.x, p.y, h0, l0);
            split2(p.z, p.w, h1, l1);
            uint2 hi = {h0, h1}, lo = {l0, l1};
            *(uint2*)&sA[row*SPAD + l]       = hi;
            *(uint2*)&sA[row*SPAD + 64 + l]  = hi;
            *(uint2*)&sA[row*SPAD + 128 + l] = lo;
        }
        CP_WAIT0();
        __syncthreads();
        #pragma unroll
        for (int k0 = 0; k0 < 192; k0 += 16) {
            uint32_t a[4], bb[4][4];
            ldm4(a, aBase + (k0 << 1));
            #pragma unroll
            for (int p = 0; p < 4; p++) ldm4(bb[p], bBase + ((p*16*SPAD + k0) << 1));
            #pragma unroll
            for (int nt = 0; nt < 8; nt++)
                mma16816(acc[nt], a, bb[nt>>1][(nt&1)*2], bb[nt>>1][(nt&1)*2+1]);
        }
    }

    const int g = lane >> 2, tg = lane & 3;
    #pragma unroll
    for (int nt = 0; nt < 8; nt++) {
        int col = h * 64 + nt*8 + tg*2;
        int r0 = mBase + wm + g;
        float2 o0 = {acc[nt][0], acc[nt][1]};
        float2 o1 = {acc[nt][2], acc[nt][3]};
        *(float2*)&g_ao[((size_t)b * S_ + r0) * DH + col] = o0;
        *(float2*)&g_ao[((size_t)b * S_ + r0 + 8) * DH + col] = o1;
    }
}

// ============================================================================
// Row softmax in place; one block per row.
// ============================================================================
__global__ __launch_bounds__(256) void softmax_kernel(float* __restrict__ attn)
{
    __shared__ float red[8];
    const int tid = threadIdx.x;
    float4* p = (float4*)(attn + (size_t)blockIdx.x * S_);
    float4 v0 = p[tid], v1 = p[tid + 256];
    float mx = fmaxf(fmaxf(fmaxf(v0.x,v0.y), fmaxf(v0.z,v0.w)),
                     fmaxf(fmaxf(v1.x,v1.y), fmaxf(v1.z,v1.w)));
    #pragma unroll
    for (int o = 16; o > 0; o >>= 1) mx = fmaxf(mx, __shfl_xor_sync(~0u, mx, o));
    if ((tid & 31) == 0) red[tid >> 5] = mx;
    __syncthreads();
    mx = red[0];
    #pragma unroll
    for (int i = 1; i < 8; i++) mx = fmaxf(mx, red[i]);
    __syncthreads();
    v0.x = __expf(v0.x - mx); v0.y = __expf(v0.y - mx);
    v0.z = __expf(v0.z - mx); v0.w = __expf(v0.w - mx);
    v1.x = __expf(v1.x - mx); v1.y = __expf(v1.y - mx);
    v1.z = __expf(v1.z - mx); v1.w = __expf(v1.w - mx);
    float s = v0.x+v0.y+v0.z+v0.w + v1.x+v1.y+v1.z+v1.w;
    #pragma unroll
    for (int o = 16; o > 0; o >>= 1) s += __shfl_xor_sync(~0u, s, o);
    if ((tid & 31) == 0) red[tid >> 5] = s;
    __syncthreads();
    s = red[0];
    #pragma unroll
    for (int i = 1; i < 8; i++) s += red[i];
    float inv = 1.f / s;
    v0.x *= inv; v0.y *= inv; v0.z *= inv; v0.w *= inv;
    v1.x *= inv; v1.y *= inv; v1.z *= inv; v1.w *= inv;
    p[tid] = v0; p[tid + 256] = v1;
}

// ============================================================================
// LayerNorm (512) per row.
// ============================================================================
__global__ __launch_bounds__(128) void ln_kernel(
    const float* __restrict__ gamma, const float* __restrict__ beta,
    float* __restrict__ out)
{
    __shared__ float red[8];
    const int r = blockIdx.x, tid = threadIdx.x;
    float4 v = *(const float4*)&g_o[(size_t)r * 512 + tid * 4];
    float s  = v.x + v.y + v.z + v.w;
    float sq = v.x*v.x + v.y*v.y + v.z*v.z + v.w*v.w;
    #pragma unroll
    for (int o = 16; o > 0; o >>= 1) {
        s  += __shfl_xor_sync(~0u, s,  o);
        sq += __shfl_xor_sync(~0u, sq, o);
    }
    if ((tid & 31) == 0) { red[tid >> 5] = s; red[4 + (tid >> 5)] = sq; }
    __syncthreads();
    if (tid < 32) {
        float a  = (tid < 4) ? red[tid]     : 0.f;
        float b2 = (tid < 4) ? red[4 + tid] : 0.f;
        #pragma unroll
        for (int o = 2; o > 0; o >>= 1) {
            a  += __shfl_xor_sync(~0u, a,  o);
            b2 += __shfl_xor_sync(~0u, b2, o);
        }
        if (tid == 0) { red[0] = a; red[1] = b2; }
    }
    __syncthreads();
    float mean = red[0] * (1.f / 512.f);
    float var  = red[1] * (1.f / 512.f) - mean * mean;
    float inv  = rsqrtf(var + 1e-5f);
    int c = tid * 4;
    float4 g4 = *(const float4*)&gamma[c];
    float4 b4 = *(const float4*)&beta[c];
    float4 o4;
    o4.x = (v.x - mean) * inv * g4.x + b4.x;
    o4.y = (v.y - mean) * inv * g4.y + b4.y;
    o4.z = (v.z - mean) * inv * g4.z + b4.z;
    o4.w = (v.w - mean) * inv * g4.w + b4.w;
    *(float4*)&out[(size_t)r * 512 + c] = o4;
}

// ============================================================================
extern "C" void kernel_launch(void* const* d_in, const int* in_sizes, int n_in,
                              void* d_out, int out_size)
{
    const float* x    = (const float*)d_in[0];
    const int*   mask = (const int*)  d_in[1];
    const float* Wq   = (const float*)d_in[2];
    const float* bq   = (const float*)d_in[3];
    const float* Wk   = (const float*)d_in[4];
    const float* bk   = (const float*)d_in[5];
    const float* Wv   = (const float*)d_in[6];
    const float* bv   = (const float*)d_in[7];
    const float* pe   = (const float*)d_in[8];
    const float* Wo   = (const float*)d_in[9];
    const float* bo   = (const float*)d_in[10];
    const float* gam  = (const float*)d_in[11];
    const float* bet  = (const float*)d_in[12];
    float* out = (float*)d_out;

    float *aop, *op, *fb;
    __nv_bfloat16 *xsp, *aosp, *wtp;
    cudaGetSymbolAddress((void**)&aop,  g_ao);
    cudaGetSymbolAddress((void**)&op,   g_o);
    cudaGetSymbolAddress((void**)&fb,   g_attn_fb);
    cudaGetSymbolAddress((void**)&xsp,  g_xs);
    cudaGetSymbolAddress((void**)&aosp, g_aos);
    cudaGetSymbolAddress((void**)&wtp,  g_wt);

    const size_t out_elems  = (size_t)M_ * DH;
    const size_t attn_elems = (size_t)BH_ * S_ * S_;
    int write_attn = ((size_t)out_size >= out_elems + attn_elems) ? 1 : 0;
    float* attn_buf = write_attn ? (out + out_elems) : fb;

    cudaFuncSetAttribute(scores_mma, cudaFuncAttributeMaxDynamicSharedMemorySize, SC_SMEM);
    cudaFuncSetAttribute(pv_mma,     cudaFuncAttributeMaxDynamicSharedMemorySize, PV_SMEM);
    cudaFuncSetAttribute(proj_mma,   cudaFuncAttributeMaxDynamicSharedMemorySize, PJ_SMEM);

    x_prep<<<M_*128/256, 256>>>(x, xsp);
    w_prep<<<dim3(8, 8, 4), 256>>>(Wq, Wk, Wv, Wo);

    // fused QKV: z=0 -> Q (mode 1), z=1 -> K (mode 2), z=2 -> V (mode 3)
    proj_mma<<<dim3(4, 64, 3), 256, PJ_SMEM>>>(xsp, wtp, bq, bk, bv, pe, nullptr, 1);
    v_prep<<<dim3(32, 32), 256>>>();

    scores_mma<<<dim3(16, 16, 32), 256, SC_SMEM>>>(mask, attn_buf);
    softmax_kernel<<<BH_*S_, 256>>>(attn_buf);
    pv_mma<<<dim3(16, 32), 256, PV_SMEM>>>(attn_buf);

    x_prep<<<M_*128/256, 256>>>(aop, aosp);
    proj_mma<<<dim3(4, 64, 1), 256, PJ_SMEM>>>(aosp, wtp + (size_t)3*512*1536,
                                               bo, bo, bo, nullptr, op, 0);
    ln_kernel<<<M_, 128>>>(gam, bet, out);
}